// round 5
// baseline (speedup 1.0000x reference)
#include <cuda_runtime.h>
#include <math.h>

// ----------------------------------------------------------------------------
// RARL2 objective via Markov-parameter (Neumann) expansion + Parseval.
//
//   err(z) = F(z) - H(z) = sum_{k=0}^{K} G'_k z^{-k},
//     G'_0 = D_F,  G'_k = C_F A_F^{k-1} B_F - (C A^{k-1})[:, :128]   (k >= 1)
//   omega = linspace(0, 2pi, 100)  =>  z_j = exp(2*pi*i*j/99), j=0..99,
//   z_99 == z_0.  Orthogonality of the 99 distinct roots gives
//   objective = ( 99 * sum_k ||G'_k||_F^2 + || sum_k G'_k ||_F^2 ) / 100.
//
// Input dtype (f32 vs f64) is detected at runtime on-device; output is written
// in the same dtype.  Input slots resolved from in_sizes (element counts).
// ----------------------------------------------------------------------------

#define NS   256
#define NF   384
#define MM   128
#define PP   128
#define STRIDE 8
#define TSTEPS 6   // K = 48 Markov parameters

// -------------------- device scratch (static, no allocs) --------------------
__device__ float2 g_Af[NF * NF];
__device__ float2 g_P2[NF * NF];
__device__ float2 g_P4[NF * NF];
__device__ float2 g_P8[NF * NF];
__device__ float2 g_A [NS * NS];
__device__ float2 g_Q2[NS * NS];
__device__ float2 g_Q4[NS * NS];
__device__ float2 g_Q8[NS * NS];
__device__ float2 g_Bf[NF * MM];
__device__ float2 g_VF[2][STRIDE * PP * NF];
__device__ float2 g_VH[2][STRIDE * PP * NS];
__device__ float2 g_G [TSTEPS * STRIDE * PP * MM];
__device__ double2 g_part[128];
__device__ int g_isDouble;

// -------------------- dtype detection ---------------------------------------
__global__ void detect_kernel(const void* probe)
{
    if (threadIdx.x != 0 || blockIdx.x != 0) return;
    const double* pd = (const double*)probe;
    int ok = 1;
    for (int i = 0; i < 32; i++) {
        double v = pd[i];
        double a = fabs(v);
        if (!isfinite(v) || a < 1e-12 || a > 1e6) { ok = 0; break; }
    }
    g_isDouble = ok;
}

__device__ __forceinline__ float ld_val(const void* p, int i)
{
    return g_isDouble ? (float)((const double*)p)[i] : ((const float*)p)[i];
}
__device__ __forceinline__ double ld_vald(const void* p, int i)
{
    return g_isDouble ? ((const double*)p)[i] : (double)((const float*)p)[i];
}

// -------------------- prep: inputs -> fp32 complex scratch -------------------
__global__ void prep_kernel(const void* Cre,  const void* Cim,
                            const void* Are,  const void* Aim,
                            const void* AFre, const void* AFim,
                            const void* BFre, const void* BFim,
                            const void* CFre, const void* CFim)
{
    int i = blockIdx.x * blockDim.x + threadIdx.x;
    if (i < NF * NF) g_Af[i]    = make_float2(ld_val(AFre, i), ld_val(AFim, i));
    if (i < NS * NS) g_A[i]     = make_float2(ld_val(Are,  i), ld_val(Aim,  i));
    if (i < NF * MM) g_Bf[i]    = make_float2(ld_val(BFre, i), ld_val(BFim, i));
    if (i < PP * NF) g_VF[0][i] = make_float2(ld_val(CFre, i), ld_val(CFim, i));
    if (i < PP * NS) g_VH[0][i] = make_float2(ld_val(Cre,  i), ld_val(Cim,  i));
}

// -------------------- generic complex GEMM: C = A*B (optionally - Sub) -------
__global__ void __launch_bounds__(128) cgemm_kernel(
    const float2* __restrict__ A, int lda,
    const float2* __restrict__ B, int ldb,
    float2* __restrict__ C, int ldc,
    int Kdim,
    const float2* __restrict__ Sub, int ldsub)
{
    __shared__ float2 As[32][32];
    __shared__ float2 Bs[32][32];

    const int tid = threadIdx.x;
    const int tx  = tid & 15;
    const int ty  = tid >> 4;
    const int rowBase = blockIdx.y << 5;
    const int colBase = blockIdx.x << 5;

    float2 acc[4][2];
#pragma unroll
    for (int i = 0; i < 4; i++) {
        acc[i][0] = make_float2(0.f, 0.f);
        acc[i][1] = make_float2(0.f, 0.f);
    }

    const float2* Ab = A + (size_t)rowBase * lda;
    const float2* Bb = B + colBase;

    for (int k0 = 0; k0 < Kdim; k0 += 32) {
#pragma unroll
        for (int l = 0; l < 8; l++) {
            int idx = tid + (l << 7);
            int r = idx >> 5;
            int c = idx & 31;
            As[r][c] = Ab[(size_t)r * lda + (k0 + c)];
            Bs[r][c] = Bb[(size_t)(k0 + r) * ldb + c];
        }
        __syncthreads();
#pragma unroll
        for (int kk = 0; kk < 32; kk++) {
            float2 b0 = Bs[kk][tx];
            float2 b1 = Bs[kk][tx + 16];
#pragma unroll
            for (int i = 0; i < 4; i++) {
                float2 a = As[(ty << 2) + i][kk];
                acc[i][0].x = fmaf(a.x, b0.x, acc[i][0].x);
                acc[i][0].x = fmaf(-a.y, b0.y, acc[i][0].x);
                acc[i][0].y = fmaf(a.x, b0.y, acc[i][0].y);
                acc[i][0].y = fmaf(a.y, b0.x, acc[i][0].y);
                acc[i][1].x = fmaf(a.x, b1.x, acc[i][1].x);
                acc[i][1].x = fmaf(-a.y, b1.y, acc[i][1].x);
                acc[i][1].y = fmaf(a.x, b1.y, acc[i][1].y);
                acc[i][1].y = fmaf(a.y, b1.x, acc[i][1].y);
            }
        }
        __syncthreads();
    }

#pragma unroll
    for (int i = 0; i < 4; i++) {
        int r = rowBase + (ty << 2) + i;
#pragma unroll
        for (int j = 0; j < 2; j++) {
            int c = colBase + tx + (j << 4);
            float2 v = acc[i][j];
            if (Sub != nullptr) {
                float2 s = Sub[(size_t)r * ldsub + c];
                v.x -= s.x;
                v.y -= s.y;
            }
            C[(size_t)r * ldc + c] = v;
        }
    }
}

// -------------------- reduction ---------------------------------------------
__global__ void reduceA_kernel(const void* __restrict__ DFre,
                               const void* __restrict__ DFim)
{
    int e = blockIdx.x * 128 + threadIdx.x;   // (p, m)
    int p = e >> 7;
    int m = e & 127;

    double sre = ld_vald(DFre, e);
    double sim = ld_vald(DFim, e);
    double nrm = sre * sre + sim * sim;

#pragma unroll 1
    for (int t = 0; t < TSTEPS; t++) {
        const float2* Gt = g_G + (size_t)t * (STRIDE * PP * MM);
#pragma unroll
        for (int r = 0; r < STRIDE; r++) {
            float2 g = Gt[(size_t)(r * PP + p) * MM + m];
            sre += (double)g.x;
            sim += (double)g.y;
            nrm += (double)g.x * (double)g.x + (double)g.y * (double)g.y;
        }
    }
    double sq = sre * sre + sim * sim;

    __shared__ double shn[128];
    __shared__ double shs[128];
    shn[threadIdx.x] = nrm;
    shs[threadIdx.x] = sq;
    __syncthreads();
    for (int o = 64; o > 0; o >>= 1) {
        if (threadIdx.x < o) {
            shn[threadIdx.x] += shn[threadIdx.x + o];
            shs[threadIdx.x] += shs[threadIdx.x + o];
        }
        __syncthreads();
    }
    if (threadIdx.x == 0) g_part[blockIdx.x] = make_double2(shn[0], shs[0]);
}

__global__ void reduceB_kernel(void* __restrict__ out)
{
    __shared__ double shn[128];
    __shared__ double shs[128];
    double2 v = g_part[threadIdx.x];
    shn[threadIdx.x] = v.x;
    shs[threadIdx.x] = v.y;
    __syncthreads();
    for (int o = 64; o > 0; o >>= 1) {
        if (threadIdx.x < o) {
            shn[threadIdx.x] += shn[threadIdx.x + o];
            shs[threadIdx.x] += shs[threadIdx.x + o];
        }
        __syncthreads();
    }
    if (threadIdx.x == 0) {
        double res = (99.0 * shn[0] + shs[0]) / 100.0;
        if (g_isDouble) ((double*)out)[0] = res;
        else            ((float*)out)[0]  = (float)res;
    }
}

// -------------------- host orchestration ------------------------------------
extern "C" void kernel_launch(void* const* d_in, const int* in_sizes, int n_in,
                              void* d_out, int out_size)
{
    (void)out_size;

    // resolve input slots by element count:
    // C = 32768, A = 65536, A_F = 147456, B_F/C_F = 49152, D_F = 16384
    int iC[2] = {0, 0}, iA[2] = {0, 0}, iAF[2] = {0, 0};
    int iBC[4] = {0, 0, 0, 0}, iDF[2] = {0, 0};
    int nC = 0, nA = 0, nAF = 0, nBC = 0, nDF = 0;
    for (int i = 0; i < n_in && i < 12; i++) {
        switch (in_sizes[i]) {
            case 32768:  if (nC  < 2) iC[nC++]   = i; break;
            case 65536:  if (nA  < 2) iA[nA++]   = i; break;
            case 147456: if (nAF < 2) iAF[nAF++] = i; break;
            case 49152:  if (nBC < 4) iBC[nBC++] = i; break;
            case 16384:  if (nDF < 2) iDF[nDF++] = i; break;
            default: break;
        }
    }
    // alphabetical ordering puts A_F_* first (imag before real); dict order
    // puts C_real first (real before imag).
    const bool imagFirst = (n_in > 0 && in_sizes[0] == 147456);
    const int re = imagFirst ? 1 : 0;
    const int im = imagFirst ? 0 : 1;

    const void* Cre  = d_in[iC[re]];
    const void* Cim  = d_in[iC[im]];
    const void* Are  = d_in[iA[re]];
    const void* Aim  = d_in[iA[im]];
    const void* AFre = d_in[iAF[re]];
    const void* AFim = d_in[iAF[im]];
    const void* BFre = d_in[iBC[0 + re]];
    const void* BFim = d_in[iBC[0 + im]];
    const void* CFre = d_in[iBC[2 + re]];
    const void* CFim = d_in[iBC[2 + im]];
    const void* DFre = d_in[iDF[re]];
    const void* DFim = d_in[iDF[im]];

    float2 *pAf, *pP2, *pP4, *pP8, *pA, *pQ2, *pQ4, *pQ8, *pBf, *pVF, *pVH, *pG;
    cudaGetSymbolAddress((void**)&pAf, g_Af);
    cudaGetSymbolAddress((void**)&pP2, g_P2);
    cudaGetSymbolAddress((void**)&pP4, g_P4);
    cudaGetSymbolAddress((void**)&pP8, g_P8);
    cudaGetSymbolAddress((void**)&pA,  g_A);
    cudaGetSymbolAddress((void**)&pQ2, g_Q2);
    cudaGetSymbolAddress((void**)&pQ4, g_Q4);
    cudaGetSymbolAddress((void**)&pQ8, g_Q8);
    cudaGetSymbolAddress((void**)&pBf, g_Bf);
    cudaGetSymbolAddress((void**)&pVF, g_VF);
    cudaGetSymbolAddress((void**)&pVH, g_VH);
    cudaGetSymbolAddress((void**)&pG,  g_G);

    float2* VF[2] = { pVF, pVF + STRIDE * PP * NF };
    float2* VH[2] = { pVH, pVH + STRIDE * PP * NS };

    // 0) detect input dtype (probe the largest buffer, safe either way)
    detect_kernel<<<1, 1>>>(AFre);

    // 1) convert inputs -> fp32 complex
    prep_kernel<<<(NF * NF + 255) / 256, 256>>>(Cre, Cim, Are, Aim, AFre, AFim,
                                                BFre, BFim, CFre, CFim);

    // 2) matrix powers by squaring
    cgemm_kernel<<<dim3(NF / 32, NF / 32), 128>>>(pAf, NF, pAf, NF, pP2, NF, NF, nullptr, 0);
    cgemm_kernel<<<dim3(NS / 32, NS / 32), 128>>>(pA,  NS, pA,  NS, pQ2, NS, NS, nullptr, 0);
    cgemm_kernel<<<dim3(NF / 32, NF / 32), 128>>>(pP2, NF, pP2, NF, pP4, NF, NF, nullptr, 0);
    cgemm_kernel<<<dim3(NS / 32, NS / 32), 128>>>(pQ2, NS, pQ2, NS, pQ4, NS, NS, nullptr, 0);
    cgemm_kernel<<<dim3(NF / 32, NF / 32), 128>>>(pP4, NF, pP4, NF, pP8, NF, NF, nullptr, 0);
    cgemm_kernel<<<dim3(NS / 32, NS / 32), 128>>>(pQ4, NS, pQ4, NS, pQ8, NS, NS, nullptr, 0);

    // 3) seeds by doubling: row-block r holds C_F*A_F^r / C*A^r, r=0..7
    cgemm_kernel<<<dim3(NF / 32, 4),  128>>>(VF[0], NF, pAf, NF, VF[0] + 128 * NF, NF, NF, nullptr, 0);
    cgemm_kernel<<<dim3(NS / 32, 4),  128>>>(VH[0], NS, pA,  NS, VH[0] + 128 * NS, NS, NS, nullptr, 0);
    cgemm_kernel<<<dim3(NF / 32, 8),  128>>>(VF[0], NF, pP2, NF, VF[0] + 256 * NF, NF, NF, nullptr, 0);
    cgemm_kernel<<<dim3(NS / 32, 8),  128>>>(VH[0], NS, pQ2, NS, VH[0] + 256 * NS, NS, NS, nullptr, 0);
    cgemm_kernel<<<dim3(NF / 32, 16), 128>>>(VF[0], NF, pP4, NF, VF[0] + 512 * NF, NF, NF, nullptr, 0);
    cgemm_kernel<<<dim3(NS / 32, 16), 128>>>(VH[0], NS, pQ4, NS, VH[0] + 512 * NS, NS, NS, nullptr, 0);

    // 4) main loop: G_t = VF*B_F - VH[:, :128];  V <- V * A^8
    int cur = 0;
    for (int t = 0; t < TSTEPS; t++) {
        cgemm_kernel<<<dim3(MM / 32, (STRIDE * PP) / 32), 128>>>(
            VF[cur], NF, pBf, MM,
            pG + (size_t)t * (STRIDE * PP * MM), MM, NF,
            VH[cur], NS);
        if (t < TSTEPS - 1) {
            cgemm_kernel<<<dim3(NF / 32, (STRIDE * PP) / 32), 128>>>(
                VF[cur], NF, pP8, NF, VF[1 - cur], NF, NF, nullptr, 0);
            cgemm_kernel<<<dim3(NS / 32, (STRIDE * PP) / 32), 128>>>(
                VH[cur], NS, pQ8, NS, VH[1 - cur], NS, NS, nullptr, 0);
            cur ^= 1;
        }
    }

    // 5) Parseval reduction (fp64, deterministic)
    reduceA_kernel<<<128, 128>>>(DFre, DFim);
    reduceB_kernel<<<1, 128>>>(d_out);
}

// round 6
// speedup vs baseline: 3.7693x; 3.7693x over previous
#include <cuda_runtime.h>
#include <math.h>

// ----------------------------------------------------------------------------
// RARL2 objective via Markov-parameter (Neumann) expansion + Parseval.
//
//   err(z) = sum_{k=0}^{K} G'_k z^{-k},  G'_0 = D_F,
//   G'_k = C_F A_F^{k-1} B_F - (C A^{k-1})[:, :128]   (k >= 1)
//   objective = ( 99 * sum_k ||G'_k||_F^2 + || sum_k G'_k ||_F^2 ) / 100.
//
// K = 16 (truncation error ~0.25^16 ~ 2e-10 relative).
// 9 launches: detect, prep, 3 power/seed levels, 2 step launches, 2 reduce.
// ----------------------------------------------------------------------------

#define NS   256
#define NF   384
#define MM   128
#define PP   128
#define STRIDE 8
#define TSTEPS 2   // K = STRIDE*TSTEPS = 16 Markov parameters

// -------------------- device scratch (static, no allocs) --------------------
__device__ float2 g_Af[NF * NF];
__device__ float2 g_P2[NF * NF];
__device__ float2 g_P4[NF * NF];
__device__ float2 g_P8[NF * NF];
__device__ float2 g_A [NS * NS];
__device__ float2 g_Q2[NS * NS];
__device__ float2 g_Q4[NS * NS];
__device__ float2 g_Q8[NS * NS];
__device__ float2 g_Bf[NF * MM];
__device__ float2 g_VF[2][STRIDE * PP * NF];
__device__ float2 g_VH[2][STRIDE * PP * NS];
__device__ float2 g_G [TSTEPS * STRIDE * PP * MM];
__device__ double2 g_part[128];
__device__ int g_isDouble;

// -------------------- dtype detection ---------------------------------------
__global__ void detect_kernel(const void* probe)
{
    if (threadIdx.x != 0 || blockIdx.x != 0) return;
    const double* pd = (const double*)probe;
    int ok = 1;
    for (int i = 0; i < 32; i++) {
        double v = pd[i];
        double a = fabs(v);
        if (!isfinite(v) || a < 1e-12 || a > 1e6) { ok = 0; break; }
    }
    g_isDouble = ok;
}

__device__ __forceinline__ float ld_val(const void* p, int i)
{
    return g_isDouble ? (float)((const double*)p)[i] : ((const float*)p)[i];
}
__device__ __forceinline__ double ld_vald(const void* p, int i)
{
    return g_isDouble ? ((const double*)p)[i] : (double)((const float*)p)[i];
}

// -------------------- prep: inputs -> fp32 complex scratch -------------------
__global__ void prep_kernel(const void* Cre,  const void* Cim,
                            const void* Are,  const void* Aim,
                            const void* AFre, const void* AFim,
                            const void* BFre, const void* BFim,
                            const void* CFre, const void* CFim)
{
    int i = blockIdx.x * blockDim.x + threadIdx.x;
    if (i < NF * NF) g_Af[i]    = make_float2(ld_val(AFre, i), ld_val(AFim, i));
    if (i < NS * NS) g_A[i]     = make_float2(ld_val(Are,  i), ld_val(Aim,  i));
    if (i < NF * MM) g_Bf[i]    = make_float2(ld_val(BFre, i), ld_val(BFim, i));
    if (i < PP * NF) g_VF[0][i] = make_float2(ld_val(CFre, i), ld_val(CFim, i));
    if (i < PP * NS) g_VH[0][i] = make_float2(ld_val(Cre,  i), ld_val(Cim,  i));
}

// -------------------- multi-segment complex GEMM -----------------------------
// Each launch carries up to 4 independent GEMM segments; blocks are assigned
// to segments by contiguous blockIdx.x ranges.  Tile 32x32, 128 threads,
// 4x2 complex outputs per thread.  C = A*B  (optionally minus Sub).
struct Seg {
    const float2* A;
    const float2* B;
    float2*       C;
    const float2* Sub;
    int lda, ldb, ldc, ldsub, K, gw, blkEnd;
};
struct Seg4 { Seg s[4]; int n; };

__global__ void __launch_bounds__(128) cgemm_multi(Seg4 segs)
{
    // segment lookup (uniform per block)
    int si = 0;
#pragma unroll
    for (int i = 0; i < 4; i++)
        if (i < segs.n && (int)blockIdx.x >= segs.s[i].blkEnd) si = i + 1;
    const Seg sg = segs.s[si];
    const int blkStart = (si == 0) ? 0 : segs.s[si - 1].blkEnd;
    const int local = blockIdx.x - blkStart;
    const int bx = local % sg.gw;       // tile col
    const int by = local / sg.gw;       // tile row

    __shared__ float2 As[32][32];
    __shared__ float2 Bs[32][32];

    const int tid = threadIdx.x;
    const int tx  = tid & 15;
    const int ty  = tid >> 4;
    const int rowBase = by << 5;
    const int colBase = bx << 5;

    float2 acc[4][2];
#pragma unroll
    for (int i = 0; i < 4; i++) {
        acc[i][0] = make_float2(0.f, 0.f);
        acc[i][1] = make_float2(0.f, 0.f);
    }

    const float2* Ab = sg.A + (size_t)rowBase * sg.lda;
    const float2* Bb = sg.B + colBase;

    for (int k0 = 0; k0 < sg.K; k0 += 32) {
#pragma unroll
        for (int l = 0; l < 8; l++) {
            int idx = tid + (l << 7);
            int r = idx >> 5;
            int c = idx & 31;
            As[r][c] = Ab[(size_t)r * sg.lda + (k0 + c)];
            Bs[r][c] = Bb[(size_t)(k0 + r) * sg.ldb + c];
        }
        __syncthreads();
#pragma unroll
        for (int kk = 0; kk < 32; kk++) {
            float2 b0 = Bs[kk][tx];
            float2 b1 = Bs[kk][tx + 16];
#pragma unroll
            for (int i = 0; i < 4; i++) {
                float2 a = As[(ty << 2) + i][kk];
                acc[i][0].x = fmaf(a.x, b0.x, acc[i][0].x);
                acc[i][0].x = fmaf(-a.y, b0.y, acc[i][0].x);
                acc[i][0].y = fmaf(a.x, b0.y, acc[i][0].y);
                acc[i][0].y = fmaf(a.y, b0.x, acc[i][0].y);
                acc[i][1].x = fmaf(a.x, b1.x, acc[i][1].x);
                acc[i][1].x = fmaf(-a.y, b1.y, acc[i][1].x);
                acc[i][1].y = fmaf(a.x, b1.y, acc[i][1].y);
                acc[i][1].y = fmaf(a.y, b1.x, acc[i][1].y);
            }
        }
        __syncthreads();
    }

#pragma unroll
    for (int i = 0; i < 4; i++) {
        int r = rowBase + (ty << 2) + i;
#pragma unroll
        for (int j = 0; j < 2; j++) {
            int c = colBase + tx + (j << 4);
            float2 v = acc[i][j];
            if (sg.Sub != nullptr) {
                float2 s = sg.Sub[(size_t)r * sg.ldsub + c];
                v.x -= s.x;
                v.y -= s.y;
            }
            sg.C[(size_t)r * sg.ldc + c] = v;
        }
    }
}

// -------------------- reduction ---------------------------------------------
__global__ void reduceA_kernel(const void* __restrict__ DFre,
                               const void* __restrict__ DFim)
{
    int e = blockIdx.x * 128 + threadIdx.x;   // (p, m)
    int p = e >> 7;
    int m = e & 127;

    double sre = ld_vald(DFre, e);
    double sim = ld_vald(DFim, e);
    double nrm = sre * sre + sim * sim;

#pragma unroll 1
    for (int t = 0; t < TSTEPS; t++) {
        const float2* Gt = g_G + (size_t)t * (STRIDE * PP * MM);
#pragma unroll
        for (int r = 0; r < STRIDE; r++) {
            float2 g = Gt[(size_t)(r * PP + p) * MM + m];
            sre += (double)g.x;
            sim += (double)g.y;
            nrm += (double)g.x * (double)g.x + (double)g.y * (double)g.y;
        }
    }
    double sq = sre * sre + sim * sim;

    __shared__ double shn[128];
    __shared__ double shs[128];
    shn[threadIdx.x] = nrm;
    shs[threadIdx.x] = sq;
    __syncthreads();
    for (int o = 64; o > 0; o >>= 1) {
        if (threadIdx.x < o) {
            shn[threadIdx.x] += shn[threadIdx.x + o];
            shs[threadIdx.x] += shs[threadIdx.x + o];
        }
        __syncthreads();
    }
    if (threadIdx.x == 0) g_part[blockIdx.x] = make_double2(shn[0], shs[0]);
}

__global__ void reduceB_kernel(void* __restrict__ out)
{
    __shared__ double shn[128];
    __shared__ double shs[128];
    double2 v = g_part[threadIdx.x];
    shn[threadIdx.x] = v.x;
    shs[threadIdx.x] = v.y;
    __syncthreads();
    for (int o = 64; o > 0; o >>= 1) {
        if (threadIdx.x < o) {
            shn[threadIdx.x] += shn[threadIdx.x + o];
            shs[threadIdx.x] += shs[threadIdx.x + o];
        }
        __syncthreads();
    }
    if (threadIdx.x == 0) {
        double res = (99.0 * shn[0] + shs[0]) / 100.0;
        if (g_isDouble) ((double*)out)[0] = res;
        else            ((float*)out)[0]  = (float)res;
    }
}

// -------------------- host helpers ------------------------------------------
static inline Seg mkseg(const float2* A, int lda, const float2* B, int ldb,
                        float2* C, int ldc, int K, int rows, int cols,
                        const float2* Sub = nullptr, int ldsub = 0)
{
    Seg s;
    s.A = A; s.B = B; s.C = C; s.Sub = Sub;
    s.lda = lda; s.ldb = ldb; s.ldc = ldc; s.ldsub = ldsub;
    s.K = K; s.gw = cols / 32; s.blkEnd = (rows / 32) * (cols / 32);
    return s;
}

static inline void launch_segs(Seg* s, int n)
{
    Seg4 packed;
    int cum = 0;
    for (int i = 0; i < n; i++) {
        cum += s[i].blkEnd;           // blkEnd currently holds block count
        packed.s[i] = s[i];
        packed.s[i].blkEnd = cum;
    }
    for (int i = n; i < 4; i++) packed.s[i] = packed.s[n - 1];
    packed.n = n;
    cgemm_multi<<<cum, 128>>>(packed);
}

// -------------------- host orchestration ------------------------------------
extern "C" void kernel_launch(void* const* d_in, const int* in_sizes, int n_in,
                              void* d_out, int out_size)
{
    (void)out_size;

    // resolve input slots by element count:
    // C = 32768, A = 65536, A_F = 147456, B_F/C_F = 49152, D_F = 16384
    int iC[2] = {0, 0}, iA[2] = {0, 0}, iAF[2] = {0, 0};
    int iBC[4] = {0, 0, 0, 0}, iDF[2] = {0, 0};
    int nC = 0, nA = 0, nAF = 0, nBC = 0, nDF = 0;
    for (int i = 0; i < n_in && i < 12; i++) {
        switch (in_sizes[i]) {
            case 32768:  if (nC  < 2) iC[nC++]   = i; break;
            case 65536:  if (nA  < 2) iA[nA++]   = i; break;
            case 147456: if (nAF < 2) iAF[nAF++] = i; break;
            case 49152:  if (nBC < 4) iBC[nBC++] = i; break;
            case 16384:  if (nDF < 2) iDF[nDF++] = i; break;
            default: break;
        }
    }
    const bool imagFirst = (n_in > 0 && in_sizes[0] == 147456);
    const int re = imagFirst ? 1 : 0;
    const int im = imagFirst ? 0 : 1;

    const void* Cre  = d_in[iC[re]];
    const void* Cim  = d_in[iC[im]];
    const void* Are  = d_in[iA[re]];
    const void* Aim  = d_in[iA[im]];
    const void* AFre = d_in[iAF[re]];
    const void* AFim = d_in[iAF[im]];
    const void* BFre = d_in[iBC[0 + re]];
    const void* BFim = d_in[iBC[0 + im]];
    const void* CFre = d_in[iBC[2 + re]];
    const void* CFim = d_in[iBC[2 + im]];
    const void* DFre = d_in[iDF[re]];
    const void* DFim = d_in[iDF[im]];

    float2 *pAf, *pP2, *pP4, *pP8, *pA, *pQ2, *pQ4, *pQ8, *pBf, *pVF, *pVH, *pG;
    cudaGetSymbolAddress((void**)&pAf, g_Af);
    cudaGetSymbolAddress((void**)&pP2, g_P2);
    cudaGetSymbolAddress((void**)&pP4, g_P4);
    cudaGetSymbolAddress((void**)&pP8, g_P8);
    cudaGetSymbolAddress((void**)&pA,  g_A);
    cudaGetSymbolAddress((void**)&pQ2, g_Q2);
    cudaGetSymbolAddress((void**)&pQ4, g_Q4);
    cudaGetSymbolAddress((void**)&pQ8, g_Q8);
    cudaGetSymbolAddress((void**)&pBf, g_Bf);
    cudaGetSymbolAddress((void**)&pVF, g_VF);
    cudaGetSymbolAddress((void**)&pVH, g_VH);
    cudaGetSymbolAddress((void**)&pG,  g_G);

    float2* VF0 = pVF;
    float2* VF1 = pVF + STRIDE * PP * NF;
    float2* VH0 = pVH;
    float2* VH1 = pVH + STRIDE * PP * NS;

    // 0) detect dtype; 1) convert inputs -> fp32 complex
    detect_kernel<<<1, 1>>>(AFre);
    prep_kernel<<<(NF * NF + 255) / 256, 256>>>(Cre, Cim, Are, Aim, AFre, AFim,
                                                BFre, BFim, CFre, CFim);

    // L1: P2 = Af^2, Q2 = A^2, VF rows[128:256) = VF[0:128)*Af, VH likewise
    {
        Seg s[4] = {
            mkseg(pAf, NF, pAf, NF, pP2, NF, NF, NF, NF),
            mkseg(pA,  NS, pA,  NS, pQ2, NS, NS, NS, NS),
            mkseg(VF0, NF, pAf, NF, VF0 + 128 * NF, NF, NF, 128, NF),
            mkseg(VH0, NS, pA,  NS, VH0 + 128 * NS, NS, NS, 128, NS),
        };
        launch_segs(s, 4);
    }
    // L2: P4 = P2^2, Q4 = Q2^2, VF rows[256:512) = VF[0:256)*P2, VH likewise
    {
        Seg s[4] = {
            mkseg(pP2, NF, pP2, NF, pP4, NF, NF, NF, NF),
            mkseg(pQ2, NS, pQ2, NS, pQ4, NS, NS, NS, NS),
            mkseg(VF0, NF, pP2, NF, VF0 + 256 * NF, NF, NF, 256, NF),
            mkseg(VH0, NS, pQ2, NS, VH0 + 256 * NS, NS, NS, 256, NS),
        };
        launch_segs(s, 4);
    }
    // L3: P8 = P4^2, Q8 = Q4^2, VF rows[512:1024) = VF[0:512)*P4, VH likewise
    {
        Seg s[4] = {
            mkseg(pP4, NF, pP4, NF, pP8, NF, NF, NF, NF),
            mkseg(pQ4, NS, pQ4, NS, pQ8, NS, NS, NS, NS),
            mkseg(VF0, NF, pP4, NF, VF0 + 512 * NF, NF, NF, 512, NF),
            mkseg(VH0, NS, pQ4, NS, VH0 + 512 * NS, NS, NS, 512, NS),
        };
        launch_segs(s, 4);
    }
    // L4: G_0 = VF0*Bf - VH0[:, :128];  VF1 = VF0*P8;  VH1 = VH0*Q8
    {
        Seg s[3] = {
            mkseg(VF0, NF, pBf, MM, pG, MM, NF, STRIDE * PP, MM, VH0, NS),
            mkseg(VF0, NF, pP8, NF, VF1, NF, NF, STRIDE * PP, NF),
            mkseg(VH0, NS, pQ8, NS, VH1, NS, NS, STRIDE * PP, NS),
        };
        launch_segs(s, 3);
    }
    // L5: G_1 = VF1*Bf - VH1[:, :128]
    {
        Seg s[1] = {
            mkseg(VF1, NF, pBf, MM, pG + STRIDE * PP * MM, MM, NF,
                  STRIDE * PP, MM, VH1, NS),
        };
        launch_segs(s, 1);
    }

    // Parseval reduction (fp64, deterministic)
    reduceA_kernel<<<128, 128>>>(DFre, DFim);
    reduceB_kernel<<<1, 128>>>(d_out);
}